// round 14
// baseline (speedup 1.0000x reference)
#include <cuda_runtime.h>
#include <cstdint>

#define H 512
#define DK 64
#define NCLASS 4
#define VOCAB 5000
#define LW 32
#define NLEAF 20000
#define NPAR 20000
#define NTOT 40000
#define DEG 4
#define NLAYER 5
#define LMAX 256
#define NB_RED 125
#define RED_CHUNK 160
#define FR 64   // H/8 fragment tiles

__device__ float g_nodeh[(size_t)NTOT * H];
__device__ float g_xepar[(size_t)NPAR * H];
__device__ float g_EbuT[(size_t)VOCAB * H];
__device__ float g_gz0[(size_t)NPAR * H];
__device__ float g_gr0[(size_t)NPAR * H];
__device__ float g_gh0[(size_t)NPAR * H];
__device__ float g_memv[(size_t)NPAR * H];
__device__ float g_mrv[(size_t)NPAR * H];
__device__ float g_zv[(size_t)NPAR * H];
// B fragments: [mat][nt(64)][k8(64)][lane(32)][reg(2)]  (Wz,Wr,Wh,Uz,Ur,Uh)
__device__ unsigned g_bfh[(size_t)6 * FR * FR * 64];
__device__ unsigned g_bfl[(size_t)6 * FR * FR * 64];
__device__ int g_lvl[NPAR];
__device__ int g_hist[LMAX], g_lstart[LMAX], g_lofs[LMAX], g_order[NPAR];
__device__ int g_nlev, g_barcnt;
__device__ volatile int g_barsense;
__device__ float g_pmax[NB_RED * H];

__device__ __forceinline__ float sigf(float x) { return 1.f / (1.f + __expf(-x)); }

__device__ __forceinline__ unsigned f2tf(float x) {
    unsigned u; asm("cvt.rna.tf32.f32 %0, %1;" : "=r"(u) : "f"(x)); return u;
}
__device__ __forceinline__ void mma8(float4& d,
    unsigned a0, unsigned a1, unsigned a2, unsigned a3, unsigned b0, unsigned b1) {
    asm("mma.sync.aligned.m16n8k8.row.col.f32.tf32.tf32.f32 "
        "{%0,%1,%2,%3},{%4,%5,%6,%7},{%8,%9},{%0,%1,%2,%3};"
        : "+f"(d.x), "+f"(d.y), "+f"(d.z), "+f"(d.w)
        : "r"(a0), "r"(a1), "r"(a2), "r"(a3), "r"(b0), "r"(b1));
}
__device__ __forceinline__ unsigned fau(float x) { return __float_as_uint(x); }
__device__ __forceinline__ void mma3u(float4& c, const unsigned* ah, const unsigned* al,
                                      uint2 bh, uint2 bl) {
    mma8(c, ah[0], ah[1], ah[2], ah[3], bh.x, bh.y);
    mma8(c, ah[0], ah[1], ah[2], ah[3], bl.x, bl.y);
    mma8(c, al[0], al[1], al[2], al[3], bh.x, bh.y);
}

// ---------------- launch 1: transpose + init ----------------
__global__ void k_setup(const float* __restrict__ E) {
    __shared__ float t[32][33];
    int x = blockIdx.x * 32 + threadIdx.x;
    int y0 = blockIdx.y * 32;
#pragma unroll
    for (int j = 0; j < 32; j += 8) {
        int y = y0 + threadIdx.y + j;
        t[threadIdx.y + j][threadIdx.x] = (x < VOCAB) ? E[(size_t)y * VOCAB + x] : 0.f;
    }
    __syncthreads();
    int xo = blockIdx.y * 32 + threadIdx.x;
    int yo0 = blockIdx.x * 32;
#pragma unroll
    for (int j = 0; j < 32; j += 8) {
        int yo = yo0 + threadIdx.y + j;
        if (yo < VOCAB) g_EbuT[(size_t)yo * H + xo] = t[threadIdx.x][threadIdx.y + j];
    }
    if (blockIdx.x == 0 && blockIdx.y == 0) {
        int tid = threadIdx.y * 32 + threadIdx.x;
        for (int i = tid; i < NPAR; i += 256) g_lvl[i] = -1;
        if (tid < LMAX) g_hist[tid] = 0;
        if (tid == 0) { g_barcnt = 0; g_barsense = 0; }
    }
}

// ---------------- launch 2: split weights into fragment-order tf32 hi/lo ----------------
__global__ void k_split(const float* __restrict__ Wz, const float* __restrict__ Wr,
                        const float* __restrict__ Wh, const float* __restrict__ Uz,
                        const float* __restrict__ Ur, const float* __restrict__ Uh) {
    int idx = blockIdx.x * 256 + threadIdx.x;      // (mat, nt, k8, lane)
    if (idx >= 6 * FR * FR * 32) return;
    int lane = idx & 31;
    int k8 = (idx >> 5) & 63;
    int nt = (idx >> 11) & 63;
    int mat = idx >> 17;
    const float* src = mat == 0 ? Wz : mat == 1 ? Wr : mat == 2 ? Wh
                     : mat == 3 ? Uz : mat == 4 ? Ur : Uh;
    int n = nt * 8 + (lane >> 2);
    int k = k8 * 8 + (lane & 3);
    float x0 = src[(size_t)n * H + k];
    float x1 = src[(size_t)n * H + k + 4];
    unsigned h0 = f2tf(x0), h1 = f2tf(x1);
    size_t o = (size_t)idx * 2;
    g_bfh[o] = h0; g_bfh[o + 1] = h1;
    g_bfl[o] = f2tf(x0 - __uint_as_float(h0));
    g_bfl[o + 1] = f2tf(x1 - __uint_as_float(h1));
}

// ---------------- launch 3: embed ----------------
__global__ void k_embed(const float* __restrict__ xw, const int* __restrict__ xi) {
    int n = blockIdx.x;
    int tid = threadIdx.x;   // 128
    __shared__ float s_w[LW];
    __shared__ int   s_i[LW];
    if (tid < LW) { s_w[tid] = xw[n * LW + tid]; s_i[tid] = xi[n * LW + tid]; }
    __syncthreads();
    float4 acc = make_float4(0.f, 0.f, 0.f, 0.f);
#pragma unroll 8
    for (int l = 0; l < LW; l++) {
        float4 e = ((const float4*)(g_EbuT + (size_t)s_i[l] * H))[tid];
        float w = s_w[l];
        acc.x += w * e.x; acc.y += w * e.y; acc.z += w * e.z; acc.w += w * e.w;
    }
    float4* dst = (n < NLEAF) ? (float4*)(g_nodeh + (size_t)n * H)
                              : (float4*)(g_xepar + (size_t)(n - NLEAF) * H);
    dst[tid] = acc;
}

// ---------------- launch 4: pre-GEMM; A smem (pipelined), B gmem frags ----------------
// BM=128, BN=64, BK=32; 8 warps = 4Mw x 2Nw; warp tile 32x32
__global__ void __launch_bounds__(256) k_pregemm(
    const float* __restrict__ bz, const float* __restrict__ br, const float* __restrict__ bh)
{
    __shared__ float SM[9216];          // A hi/lo, 128 rows x stride 36
    float* sAh = SM;
    float* sAl = SM + 4608;
    int mat = blockIdx.y;
    const float* bias = mat == 0 ? bz : mat == 1 ? br : bh;
    float* out = mat == 0 ? g_gz0 : mat == 1 ? g_gr0 : g_gh0;
    int n0 = blockIdx.x * 64, m0 = blockIdx.z * 128;
    int tid = threadIdx.x;
    int w = tid >> 5, lane = tid & 31;
    int wm = w >> 1, wn = w & 1;
    float4 c[2][4];
#pragma unroll
    for (int i = 0; i < 2; i++)
#pragma unroll
        for (int j = 0; j < 4; j++) c[i][j] = make_float4(0.f, 0.f, 0.f, 0.f);
    int arow = tid >> 1, akq = (tid & 1) * 16;
    int xm = min(m0 + arow, NPAR - 1);
    const float* xr = g_xepar + (size_t)xm * H + akq;
    // prologue: load kc=0 slice
    float4 v[4];
#pragma unroll
    for (int q = 0; q < 4; q++) v[q] = __ldg((const float4*)(xr + q * 4));
    for (int kc = 0; kc < H; kc += 32) {
        // stage current slice
#pragma unroll
        for (int q = 0; q < 4; q++) {
            float vv[4] = {v[q].x, v[q].y, v[q].z, v[q].w};
#pragma unroll
            for (int j = 0; j < 4; j++) {
                int o = arow * 36 + akq + q * 4 + j;
                unsigned h = f2tf(vv[j]);
                sAh[o] = __uint_as_float(h);
                sAl[o] = __uint_as_float(f2tf(vv[j] - __uint_as_float(h)));
            }
        }
        __syncthreads();
        // prefetch next slice (overlaps with MMA work below)
        if (kc + 32 < H) {
#pragma unroll
            for (int q = 0; q < 4; q++)
                v[q] = __ldg((const float4*)(xr + kc + 32 + q * 4));
        }
#pragma unroll
        for (int k8 = 0; k8 < 4; k8++) {
            unsigned ah[2][4], al[2][4];
#pragma unroll
            for (int mt = 0; mt < 2; mt++) {
                int ab = (wm * 32 + mt * 16 + (lane >> 2)) * 36 + k8 * 8 + (lane & 3);
                ah[mt][0] = fau(sAh[ab]);     ah[mt][1] = fau(sAh[ab + 288]);
                ah[mt][2] = fau(sAh[ab + 4]); ah[mt][3] = fau(sAh[ab + 292]);
                al[mt][0] = fau(sAl[ab]);     al[mt][1] = fau(sAl[ab + 288]);
                al[mt][2] = fau(sAl[ab + 4]); al[mt][3] = fau(sAl[ab + 292]);
            }
#pragma unroll
            for (int nt = 0; nt < 4; nt++) {
                size_t fo = (((size_t)mat * FR + (n0 >> 3) + wn * 4 + nt) * FR
                             + (kc >> 3) + k8) * 64 + lane * 2;
                uint2 bh2 = __ldg((const uint2*)&g_bfh[fo]);
                uint2 bl2 = __ldg((const uint2*)&g_bfl[fo]);
                mma3u(c[0][nt], ah[0], al[0], bh2, bl2);
                mma3u(c[1][nt], ah[1], al[1], bh2, bl2);
            }
        }
        __syncthreads();
    }
#pragma unroll
    for (int mt = 0; mt < 2; mt++)
#pragma unroll
    for (int nt = 0; nt < 4; nt++) {
        float vals[4] = {c[mt][nt].x, c[mt][nt].y, c[mt][nt].z, c[mt][nt].w};
#pragma unroll
        for (int rr = 0; rr < 2; rr++) {
            int m = m0 + (wm * 2 + mt) * 16 + (lane >> 2) + rr * 8;
            if (m >= NPAR) continue;
#pragma unroll
            for (int cc = 0; cc < 2; cc++) {
                int d = n0 + (wn * 4 + nt) * 8 + 2 * (lane & 3) + cc;
                out[(size_t)m * H + d] = vals[rr * 2 + cc] + bias[d];
            }
        }
    }
}

// ---------------- launch 5: persistent level-synchronous main ----------------
__device__ __forceinline__ void gridbar(int nb, int& sense) {
    __syncthreads();
    if (threadIdx.x == 0) {
        sense ^= 1;
        __threadfence();
        if (atomicAdd(&g_barcnt, 1) == nb - 1) {
            atomicExch(&g_barcnt, 0);
            __threadfence();
            g_barsense = sense;
        } else {
            while (g_barsense != sense) __nanosleep(32);
        }
        __threadfence();
    }
    __syncthreads();
}

#define AH(buf,k,head) (((buf)*4+(k))*8+(head))*65

__device__ int attn_core(int p, const int* __restrict__ tree, float* SBUF,
                         int* s_child, float* s_sc, float* s_p) {
    int tid = threadIdx.x;
    __syncthreads();
    if (tid < DEG) s_child[tid] = tree[p * DEG + tid];
    __syncthreads();
#pragma unroll
    for (int j = 0; j < 8; j++) {
        int idx = tid + j * 256;
        int k = idx >> 9, col = idx & 511, head = col >> 6, d = col & 63;
        int c = s_child[k];
        SBUF[AH(0, k, head) + d] = (c > -1) ? __ldcg(&g_nodeh[(size_t)c * H + col]) : 0.f;
    }
    __syncthreads();
    int cur = 0;
    for (int layer = 0; layer < NLAYER; layer++) {
        if (tid < 128) {
            int head = tid >> 4, q = (tid >> 2) & 3, kk = tid & 3;
            const float* hq = &SBUF[AH(cur, q, head)];
            const float* hk = &SBUF[AH(cur, kk, head)];
            float s = 0.f;
#pragma unroll
            for (int d = 0; d < DK; d++) s += hq[d] * hk[d];
            s *= 0.125f;
            if (s_child[kk] <= -1) s = -1e9f;
            s_sc[(head * 4 + q) * 4 + kk] = s;
        }
        __syncthreads();
        if (tid < 32) {
            int head = tid >> 2, q = tid & 3;
            const float* r = &s_sc[(head * 4 + q) * 4];
            float m = fmaxf(fmaxf(r[0], r[1]), fmaxf(r[2], r[3]));
            float e0 = __expf(r[0] - m), e1 = __expf(r[1] - m);
            float e2 = __expf(r[2] - m), e3 = __expf(r[3] - m);
            float inv = 1.f / (e0 + e1 + e2 + e3);
            float* pr = &s_p[(head * 4 + q) * 4];
            pr[0] = e0 * inv; pr[1] = e1 * inv; pr[2] = e2 * inv; pr[3] = e3 * inv;
        }
        __syncthreads();
        int nxt = cur ^ 1;
#pragma unroll
        for (int j = 0; j < 2; j++) {
            int col = tid + j * 256, head = col >> 6, d = col & 63;
            float v0 = SBUF[AH(cur, 0, head) + d];
            float v1 = SBUF[AH(cur, 1, head) + d];
            float v2 = SBUF[AH(cur, 2, head) + d];
            float v3 = SBUF[AH(cur, 3, head) + d];
#pragma unroll
            for (int q = 0; q < 4; q++) {
                const float* pr = &s_p[(head * 4 + q) * 4];
                SBUF[AH(nxt, q, head) + d] = pr[0] * v0 + pr[1] * v1 + pr[2] * v2 + pr[3] * v3;
            }
        }
        __syncthreads();
        cur = nxt;
    }
    return cur;
}

__device__ void phaseA(int row, const int* __restrict__ tree, float* SBUF,
                       int* s_child, float* s_sc, float* s_p) {
    int tid = threadIdx.x;
    int p = g_order[row];
    int cur = attn_core(p, tree, SBUF, s_child, s_sc, s_p);
    int cc = (s_child[0] > -1) + (s_child[1] > -1) + (s_child[2] > -1) + (s_child[3] > -1);
    float denom = (float)max(cc, 1);
#pragma unroll
    for (int j = 0; j < 2; j++) {
        int col = tid + j * 256, head = col >> 6, d = col & 63;
        float m = 0.f;
#pragma unroll
        for (int k = 0; k < DEG; k++)
            if (s_child[k] > -1) m += SBUF[AH(cur, k, head) + d];
        __stcg(&g_memv[(size_t)row * H + col], m / denom);
    }
}

// cooperative fp32 matvec path for tiny levels
__device__ void coopB(int start, int cnt, const float* __restrict__ Uz,
                      const float* __restrict__ Ur) {
    int gw = blockIdx.x * 8 + (threadIdx.x >> 5);
    int nw = gridDim.x * 8;
    int lane = threadIdx.x & 31;
    int ntask = cnt * H;
    for (int t = gw; t < ntask; t += nw) {
        int i = t >> 9, d = t & 511;
        int row = start + i;
        const float4* mv = (const float4*)&g_memv[(size_t)row * H];
        const float4* uz = (const float4*)(Uz + (size_t)d * H);
        const float4* ur = (const float4*)(Ur + (size_t)d * H);
        float az = 0.f, ar = 0.f;
#pragma unroll
        for (int j = 0; j < 4; j++) {
            float4 m = __ldcg(&mv[lane + j * 32]);
            float4 a = __ldg(&uz[lane + j * 32]);
            az += a.x * m.x + a.y * m.y + a.z * m.z + a.w * m.w;
            float4 b = __ldg(&ur[lane + j * 32]);
            ar += b.x * m.x + b.y * m.y + b.z * m.z + b.w * m.w;
        }
#pragma unroll
        for (int o = 16; o; o >>= 1) {
            az += __shfl_down_sync(0xffffffffu, az, o);
            ar += __shfl_down_sync(0xffffffffu, ar, o);
        }
        if (lane == 0) {
            int p = g_order[row];
            size_t rb = (size_t)row * H + d;
            float z = sigf(__ldcg(&g_gz0[(size_t)p * H + d]) + az);
            float r = sigf(__ldcg(&g_gr0[(size_t)p * H + d]) + ar);
            float mem = __ldcg(&g_memv[rb]);
            __stcg(&g_zv[rb], z);
            __stcg(&g_mrv[rb], mem * r);
        }
    }
}

__device__ void coopC(int start, int cnt, const float* __restrict__ Uh) {
    int gw = blockIdx.x * 8 + (threadIdx.x >> 5);
    int nw = gridDim.x * 8;
    int lane = threadIdx.x & 31;
    int ntask = cnt * H;
    for (int t = gw; t < ntask; t += nw) {
        int i = t >> 9, d = t & 511;
        int row = start + i;
        const float4* mrv = (const float4*)&g_mrv[(size_t)row * H];
        const float4* uh = (const float4*)(Uh + (size_t)d * H);
        float ah = 0.f;
#pragma unroll
        for (int j = 0; j < 4; j++) {
            float4 m = __ldcg(&mrv[lane + j * 32]);
            float4 a = __ldg(&uh[lane + j * 32]);
            ah += a.x * m.x + a.y * m.y + a.z * m.z + a.w * m.w;
        }
#pragma unroll
        for (int o = 16; o; o >>= 1) ah += __shfl_down_sync(0xffffffffu, ah, o);
        if (lane == 0) {
            int p = g_order[row];
            size_t rb = (size_t)row * H + d;
            float c = tanhf(__ldcg(&g_gh0[(size_t)p * H + d]) + ah);
            float z = __ldcg(&g_zv[rb]);
            float mem = __ldcg(&g_memv[rb]);
            __stcg(&g_nodeh[(size_t)(NLEAF + p) * H + d], z * mem + (1.f - z) * c);
        }
    }
}

// phaseB: BM=32, BN=64; Uz(mat3)+Ur(mat4); B from gmem frags; pipelined A
__device__ void phaseB(int start, int cnt, int t, float* SBUF, int* s_pid) {
    int tid = threadIdx.x;
    int m0 = (t >> 3) * 32, n0 = (t & 7) * 64;
    float* sAh = SBUF;            // 32*36
    float* sAl = SBUF + 1152;
    int w = tid >> 5, lane = tid & 31;
    int mat = w >> 2, ntb = (w & 3) * 2;
    float4 c[2][2];
#pragma unroll
    for (int i = 0; i < 2; i++)
#pragma unroll
        for (int j = 0; j < 2; j++) c[i][j] = make_float4(0.f, 0.f, 0.f, 0.f);
    __syncthreads();
    if (tid < 32) s_pid[tid] = g_order[start + min(m0 + tid, cnt - 1)];
    int arow = tid >> 3, ak = (tid & 7) * 4;
    int rrow = start + min(m0 + arow, cnt - 1);
    const float* aptr = &g_memv[(size_t)rrow * H + ak];
    float4 a = __ldcg((const float4*)aptr);
    for (int kc = 0; kc < H; kc += 32) {
        float av[4] = {a.x, a.y, a.z, a.w};
#pragma unroll
        for (int j = 0; j < 4; j++) {
            int o = arow * 36 + ak + j;
            unsigned h = f2tf(av[j]);
            sAh[o] = __uint_as_float(h);
            sAl[o] = __uint_as_float(f2tf(av[j] - __uint_as_float(h)));
        }
        __syncthreads();
        if (kc + 32 < H) a = __ldcg((const float4*)(aptr + kc + 32));
#pragma unroll
        for (int k8 = 0; k8 < 4; k8++) {
            unsigned ah[2][4], al[2][4];
#pragma unroll
            for (int mt = 0; mt < 2; mt++) {
                int ab = (mt * 16 + (lane >> 2)) * 36 + k8 * 8 + (lane & 3);
                ah[mt][0] = fau(sAh[ab]);     ah[mt][1] = fau(sAh[ab + 288]);
                ah[mt][2] = fau(sAh[ab + 4]); ah[mt][3] = fau(sAh[ab + 292]);
                al[mt][0] = fau(sAl[ab]);     al[mt][1] = fau(sAl[ab + 288]);
                al[mt][2] = fau(sAl[ab + 4]); al[mt][3] = fau(sAl[ab + 292]);
            }
#pragma unroll
            for (int nt2 = 0; nt2 < 2; nt2++) {
                size_t fo = (((size_t)(3 + mat) * FR + (n0 >> 3) + ntb + nt2) * FR
                             + (kc >> 3) + k8) * 64 + lane * 2;
                uint2 bh2 = __ldg((const uint2*)&g_bfh[fo]);
                uint2 bl2 = __ldg((const uint2*)&g_bfl[fo]);
                mma3u(c[0][nt2], ah[0], al[0], bh2, bl2);
                mma3u(c[1][nt2], ah[1], al[1], bh2, bl2);
            }
        }
        __syncthreads();
    }
#pragma unroll
    for (int mt = 0; mt < 2; mt++)
#pragma unroll
    for (int nt2 = 0; nt2 < 2; nt2++) {
        float vals[4] = {c[mt][nt2].x, c[mt][nt2].y, c[mt][nt2].z, c[mt][nt2].w};
#pragma unroll
        for (int rr = 0; rr < 2; rr++) {
            int rl = mt * 16 + (lane >> 2) + rr * 8;
            if (m0 + rl >= cnt) continue;
            int p = s_pid[rl];
#pragma unroll
            for (int cc2 = 0; cc2 < 2; cc2++) {
                int d = n0 + (ntb + nt2) * 8 + 2 * (lane & 3) + cc2;
                size_t rb = (size_t)(start + m0 + rl) * H + d;
                size_t pb = (size_t)p * H + d;
                float acc = vals[rr * 2 + cc2];
                if (mat == 0) {
                    __stcg(&g_zv[rb], sigf(__ldcg(&g_gz0[pb]) + acc));
                } else {
                    float r = sigf(__ldcg(&g_gr0[pb]) + acc);
                    __stcg(&g_mrv[rb], __ldcg(&g_memv[rb]) * r);
                }
            }
        }
    }
}

// phaseC: BM=32, BN=128, Uh(mat5); B from gmem frags; pipelined A
__device__ void phaseC(int start, int cnt, int t, float* SBUF, int* s_pid) {
    int tid = threadIdx.x;
    int m0 = (t >> 2) * 32, n0 = (t & 3) * 128;
    float* sAh = SBUF;
    float* sAl = SBUF + 1152;
    int w = tid >> 5, lane = tid & 31;
    int ntb = w * 2;
    float4 c[2][2];
#pragma unroll
    for (int i = 0; i < 2; i++)
#pragma unroll
        for (int j = 0; j < 2; j++) c[i][j] = make_float4(0.f, 0.f, 0.f, 0.f);
    __syncthreads();
    if (tid < 32) s_pid[tid] = g_order[start + min(m0 + tid, cnt - 1)];
    int arow = tid >> 3, ak = (tid & 7) * 4;
    int rrow = start + min(m0 + arow, cnt - 1);
    const float* aptr = &g_mrv[(size_t)rrow * H + ak];
    float4 a = __ldcg((const float4*)aptr);
    for (int kc = 0; kc < H; kc += 32) {
        float av[4] = {a.x, a.y, a.z, a.w};
#pragma unroll
        for (int j = 0; j < 4; j++) {
            int o = arow * 36 + ak + j;
            unsigned h = f2tf(av[j]);
            sAh[o] = __uint_as_float(h);
            sAl[o] = __uint_as_float(f2tf(av[j] - __uint_as_float(h)));
        }
        __syncthreads();
        if (kc + 32 < H) a = __ldcg((const float4*)(aptr + kc + 32));
#pragma unroll
        for (int k8 = 0; k8 < 4; k8++) {
            unsigned ah[2][4], al[2][4];
#pragma unroll
            for (int mt = 0; mt < 2; mt++) {
                int ab = (mt * 16 + (lane >> 2)) * 36 + k8 * 8 + (lane & 3);
                ah[mt][0] = fau(sAh[ab]);     ah[mt][1] = fau(sAh[ab + 288]);
                ah[mt][2] = fau(sAh[ab + 4]); ah[mt][3] = fau(sAh[ab + 292]);
                al[mt][0] = fau(sAl[ab]);     al[mt][1] = fau(sAl[ab + 288]);
                al[mt][2] = fau(sAl[ab + 4]); al[mt][3] = fau(sAl[ab + 292]);
            }
#pragma unroll
            for (int nt2 = 0; nt2 < 2; nt2++) {
                size_t fo = (((size_t)5 * FR + (n0 >> 3) + ntb + nt2) * FR
                             + (kc >> 3) + k8) * 64 + lane * 2;
                uint2 bh2 = __ldg((const uint2*)&g_bfh[fo]);
                uint2 bl2 = __ldg((const uint2*)&g_bfl[fo]);
                mma3u(c[0][nt2], ah[0], al[0], bh2, bl2);
                mma3u(c[1][nt2], ah[1], al[1], bh2, bl2);
            }
        }
        __syncthreads();
    }
#pragma unroll
    for (int mt = 0; mt < 2; mt++)
#pragma unroll
    for (int nt2 = 0; nt2 < 2; nt2++) {
        float vals[4] = {c[mt][nt2].x, c[mt][nt2].y, c[mt][nt2].z, c[mt][nt2].w};
#pragma unroll
        for (int rr = 0; rr < 2; rr++) {
            int rl = mt * 16 + (lane >> 2) + rr * 8;
            if (m0 + rl >= cnt) continue;
            int p = s_pid[rl];
#pragma unroll
            for (int cc2 = 0; cc2 < 2; cc2++) {
                int d = n0 + (ntb + nt2) * 8 + 2 * (lane & 3) + cc2;
                size_t rb = (size_t)(start + m0 + rl) * H + d;
                size_t pb = (size_t)p * H + d;
                float cval = tanhf(__ldcg(&g_gh0[pb]) + vals[rr * 2 + cc2]);
                float z = __ldcg(&g_zv[rb]);
                float mem = __ldcg(&g_memv[rb]);
                __stcg(&g_nodeh[(size_t)(NLEAF + p) * H + d], z * mem + (1.f - z) * cval);
            }
        }
    }
}

__global__ void __launch_bounds__(256) k_main(
    const int* __restrict__ tree,
    const float* __restrict__ Uz, const float* __restrict__ Ur,
    const float* __restrict__ Uh)
{
    __shared__ float SBUF[4608];
    __shared__ float s_sc[128], s_p[128];
    __shared__ int s_child[DEG], s_pid[32];
    int nb = gridDim.x;
    int sense = 0;
    int tid = threadIdx.x;
    int gstride = nb * 256;

    // ---- leveling prologue ----
    for (int p = blockIdx.x * 256 + tid; p < NPAR; p += gstride) {
        int lv = 0;
#pragma unroll
        for (int k = 0; k < DEG; k++) {
            int c = tree[p * DEG + k];
            if (c >= NLEAF) {
                int v;
                while ((v = atomicAdd(&g_lvl[c - NLEAF], 0)) < 0) __nanosleep(40);
                lv = max(lv, v + 1);
            }
        }
        if (lv > LMAX - 1) lv = LMAX - 1;
        atomicExch(&g_lvl[p], lv);
    }
    gridbar(nb, sense);
    for (int p = blockIdx.x * 256 + tid; p < NPAR; p += gstride)
        atomicAdd(&g_hist[g_lvl[p]], 1);
    gridbar(nb, sense);
    if (blockIdx.x == 0 && tid == 0) {
        int acc = 0, nl = 1;
        for (int i = 0; i < LMAX; i++) {
            g_lstart[i] = acc; g_lofs[i] = acc;
            acc += g_hist[i];
            if (g_hist[i] > 0) nl = i + 1;
        }
        g_nlev = nl;
    }
    gridbar(nb, sense);
    for (int p = blockIdx.x * 256 + tid; p < NPAR; p += gstride)
        g_order[atomicAdd(&g_lofs[g_lvl[p]], 1)] = p;
    gridbar(nb, sense);

    int nlev = g_nlev;
    for (int l = 0; l < nlev; l++) {
        int start = g_lstart[l], cnt = g_hist[l];
        if (cnt == 0) continue;
        for (int j = blockIdx.x; j < cnt; j += nb)
            phaseA(start + j, tree, SBUF, s_child, s_sc, s_p);
        gridbar(nb, sense);
        if (cnt < 32) {
            coopB(start, cnt, Uz, Ur);
            gridbar(nb, sense);
            coopC(start, cnt, Uh);
            gridbar(nb, sense);
        } else {
            int mt = (cnt + 31) >> 5;
            int ntB = mt * 8;
            for (int t = blockIdx.x; t < ntB; t += nb)
                phaseB(start, cnt, t, SBUF, s_pid);
            gridbar(nb, sense);
            int ntC = mt * 4;
            for (int t = blockIdx.x; t < ntC; t += nb)
                phaseC(start, cnt, t, SBUF, s_pid);
            gridbar(nb, sense);
        }
    }
}

// ---------------- reductions ----------------
__global__ void k_redmax() {
    int tid = threadIdx.x;
    int b = blockIdx.x;
    const float* base = g_nodeh + (size_t)NLEAF * H;
    float m = -3.4e38f;
    for (int p = b * RED_CHUNK; p < (b + 1) * RED_CHUNK; p++)
        m = fmaxf(m, base[(size_t)p * H + tid]);
    g_pmax[b * H + tid] = m;
}

__global__ void k_final(const float* __restrict__ Wo, const float* __restrict__ bo,
                        float* __restrict__ out) {
    __shared__ float s_f[H];
    __shared__ float s_logit[NCLASS];
    int tid = threadIdx.x;   // 512
    float m = g_pmax[tid];
    for (int b = 1; b < NB_RED; b++) m = fmaxf(m, g_pmax[b * H + tid]);
    s_f[tid] = m;
    __syncthreads();
    int w = tid >> 5, lane = tid & 31;
    if (w < NCLASS) {
        float acc = 0.f;
        for (int j = lane; j < H; j += 32) acc += Wo[w * H + j] * s_f[j];
#pragma unroll
        for (int o = 16; o; o >>= 1) acc += __shfl_down_sync(0xffffffffu, acc, o);
        if (lane == 0) s_logit[w] = acc + bo[w];
    }
    __syncthreads();
    if (tid == 0) {
        float mx = s_logit[0];
        for (int i = 1; i < NCLASS; i++) mx = fmaxf(mx, s_logit[i]);
        float e[NCLASS], s = 0.f;
        for (int i = 0; i < NCLASS; i++) { e[i] = __expf(s_logit[i] - mx); s += e[i]; }
        for (int i = 0; i < NCLASS; i++) out[i] = e[i] / s;
    }
}

extern "C" void kernel_launch(void* const* d_in, const int* in_sizes, int n_in,
                              void* d_out, int out_size) {
    const float* x_word  = (const float*)d_in[0];
    const int*   x_index = (const int*)  d_in[1];
    const int*   tree    = (const int*)  d_in[2];
    const float* E_bu    = (const float*)d_in[3];
    const float* W_z = (const float*)d_in[4];
    const float* U_z = (const float*)d_in[5];
    const float* b_z = (const float*)d_in[6];
    const float* W_r = (const float*)d_in[7];
    const float* U_r = (const float*)d_in[8];
    const float* b_r = (const float*)d_in[9];
    const float* W_h = (const float*)d_in[10];
    const float* U_h = (const float*)d_in[11];
    const float* b_h = (const float*)d_in[12];
    const float* W_out = (const float*)d_in[13];
    const float* b_out = (const float*)d_in[14];
    float* out = (float*)d_out;

    static int nb_main = 0;
    if (nb_main == 0) {
        int dev = 0; cudaGetDevice(&dev);
        int nsm = 0; cudaDeviceGetAttribute(&nsm, cudaDevAttrMultiProcessorCount, dev);
        int perSM = 0;
        cudaOccupancyMaxActiveBlocksPerMultiprocessor(&perSM, k_main, 256, 0);
        if (perSM < 1) perSM = 1;
        nb_main = nsm * perSM;
    }

    dim3 tb(32, 8), tg((VOCAB + 31) / 32, H / 32);
    k_setup<<<tg, tb>>>(E_bu);
    k_split<<<(6 * FR * FR * 32 + 255) / 256, 256>>>(W_z, W_r, W_h, U_z, U_r, U_h);
    k_embed<<<NTOT, 128>>>(x_word, x_index);
    k_pregemm<<<dim3(H / 64, 3, (NPAR + 127) / 128), 256>>>(b_z, b_r, b_h);
    k_main<<<nb_main, 256>>>(tree, U_z, U_r, U_h);
    k_redmax<<<NB_RED, H>>>();
    k_final<<<1, H>>>(W_out, b_out, out);
}

// round 15
// speedup vs baseline: 1.4959x; 1.4959x over previous
#include <cuda_runtime.h>
#include <cstdint>

#define H 512
#define DK 64
#define NCLASS 4
#define VOCAB 5000
#define LW 32
#define NLEAF 20000
#define NPAR 20000
#define NTOT 40000
#define DEG 4
#define NLAYER 5
#define LMAX 256
#define NB_RED 125
#define RED_CHUNK 160
#define FR 64   // H/8 fragment tiles

__device__ float g_nodeh[(size_t)NTOT * H];
__device__ float g_xepar[(size_t)NPAR * H];
__device__ float g_EbuT[(size_t)VOCAB * H];
__device__ float g_gz0[(size_t)NPAR * H];
__device__ float g_gr0[(size_t)NPAR * H];
__device__ float g_gh0[(size_t)NPAR * H];
__device__ float g_memv[(size_t)NPAR * H];
__device__ float g_mrv[(size_t)NPAR * H];
__device__ float g_zv[(size_t)NPAR * H];
// B fragments: [mat][nt(64)][k8(64)][lane(32)][reg(2)]  (Wz,Wr,Wh,Uz,Ur,Uh)
__device__ unsigned g_bfh[(size_t)6 * FR * FR * 64];
__device__ unsigned g_bfl[(size_t)6 * FR * FR * 64];
__device__ int g_lvl[NPAR];
__device__ int g_hist[LMAX], g_lstart[LMAX], g_lofs[LMAX], g_order[NPAR];
__device__ int g_nlev, g_barcnt;
__device__ volatile int g_barsense;
__device__ float g_pmax[NB_RED * H];

__device__ __forceinline__ float sigf(float x) { return 1.f / (1.f + __expf(-x)); }

__device__ __forceinline__ unsigned f2tf(float x) {
    unsigned u; asm("cvt.rna.tf32.f32 %0, %1;" : "=r"(u) : "f"(x)); return u;
}
__device__ __forceinline__ void mma8(float4& d,
    unsigned a0, unsigned a1, unsigned a2, unsigned a3, unsigned b0, unsigned b1) {
    asm("mma.sync.aligned.m16n8k8.row.col.f32.tf32.tf32.f32 "
        "{%0,%1,%2,%3},{%4,%5,%6,%7},{%8,%9},{%0,%1,%2,%3};"
        : "+f"(d.x), "+f"(d.y), "+f"(d.z), "+f"(d.w)
        : "r"(a0), "r"(a1), "r"(a2), "r"(a3), "r"(b0), "r"(b1));
}
__device__ __forceinline__ unsigned fau(float x) { return __float_as_uint(x); }
__device__ __forceinline__ void mma3u(float4& c, const unsigned* ah, const unsigned* al,
                                      uint2 bh, uint2 bl) {
    mma8(c, ah[0], ah[1], ah[2], ah[3], bh.x, bh.y);
    mma8(c, ah[0], ah[1], ah[2], ah[3], bl.x, bl.y);
    mma8(c, al[0], al[1], al[2], al[3], bh.x, bh.y);
}

// ---------------- launch 1: transpose + init ----------------
__global__ void k_setup(const float* __restrict__ E) {
    __shared__ float t[32][33];
    int x = blockIdx.x * 32 + threadIdx.x;
    int y0 = blockIdx.y * 32;
#pragma unroll
    for (int j = 0; j < 32; j += 8) {
        int y = y0 + threadIdx.y + j;
        t[threadIdx.y + j][threadIdx.x] = (x < VOCAB) ? E[(size_t)y * VOCAB + x] : 0.f;
    }
    __syncthreads();
    int xo = blockIdx.y * 32 + threadIdx.x;
    int yo0 = blockIdx.x * 32;
#pragma unroll
    for (int j = 0; j < 32; j += 8) {
        int yo = yo0 + threadIdx.y + j;
        if (yo < VOCAB) g_EbuT[(size_t)yo * H + xo] = t[threadIdx.x][threadIdx.y + j];
    }
    if (blockIdx.x == 0 && blockIdx.y == 0) {
        int tid = threadIdx.y * 32 + threadIdx.x;
        for (int i = tid; i < NPAR; i += 256) g_lvl[i] = -1;
        if (tid < LMAX) g_hist[tid] = 0;
        if (tid == 0) { g_barcnt = 0; g_barsense = 0; }
    }
}

// ---------------- launch 2: split weights into fragment-order tf32 hi/lo ----------------
__global__ void k_split(const float* __restrict__ Wz, const float* __restrict__ Wr,
                        const float* __restrict__ Wh, const float* __restrict__ Uz,
                        const float* __restrict__ Ur, const float* __restrict__ Uh) {
    int idx = blockIdx.x * 256 + threadIdx.x;      // (mat, nt, k8, lane)
    if (idx >= 6 * FR * FR * 32) return;
    int lane = idx & 31;
    int k8 = (idx >> 5) & 63;
    int nt = (idx >> 11) & 63;
    int mat = idx >> 17;
    const float* src = mat == 0 ? Wz : mat == 1 ? Wr : mat == 2 ? Wh
                     : mat == 3 ? Uz : mat == 4 ? Ur : Uh;
    int n = nt * 8 + (lane >> 2);
    int k = k8 * 8 + (lane & 3);
    float x0 = src[(size_t)n * H + k];
    float x1 = src[(size_t)n * H + k + 4];
    unsigned h0 = f2tf(x0), h1 = f2tf(x1);
    size_t o = (size_t)idx * 2;
    g_bfh[o] = h0; g_bfh[o + 1] = h1;
    g_bfl[o] = f2tf(x0 - __uint_as_float(h0));
    g_bfl[o + 1] = f2tf(x1 - __uint_as_float(h1));
}

// ---------------- launch 3: embed ----------------
__global__ void k_embed(const float* __restrict__ xw, const int* __restrict__ xi) {
    int n = blockIdx.x;
    int tid = threadIdx.x;   // 128
    __shared__ float s_w[LW];
    __shared__ int   s_i[LW];
    if (tid < LW) { s_w[tid] = xw[n * LW + tid]; s_i[tid] = xi[n * LW + tid]; }
    __syncthreads();
    float4 acc = make_float4(0.f, 0.f, 0.f, 0.f);
#pragma unroll 8
    for (int l = 0; l < LW; l++) {
        float4 e = ((const float4*)(g_EbuT + (size_t)s_i[l] * H))[tid];
        float w = s_w[l];
        acc.x += w * e.x; acc.y += w * e.y; acc.z += w * e.z; acc.w += w * e.w;
    }
    float4* dst = (n < NLEAF) ? (float4*)(g_nodeh + (size_t)n * H)
                              : (float4*)(g_xepar + (size_t)(n - NLEAF) * H);
    dst[tid] = acc;
}

// ---------------- launch 4: pre-GEMM; A smem, B gmem frags ----------------
// BM=128, BN=64, BK=32; 8 warps = 4Mw x 2Nw; warp tile 32x32
__global__ void __launch_bounds__(256, 3) k_pregemm(
    const float* __restrict__ bz, const float* __restrict__ br, const float* __restrict__ bh)
{
    __shared__ float SM[9216];          // A hi/lo, 128 rows x stride 36
    float* sAh = SM;
    float* sAl = SM + 4608;
    int mat = blockIdx.z;
    const float* bias = mat == 0 ? bz : mat == 1 ? br : bh;
    float* out = mat == 0 ? g_gz0 : mat == 1 ? g_gr0 : g_gh0;
    int m0 = blockIdx.x * 128, n0 = blockIdx.y * 64;
    int tid = threadIdx.x;
    int w = tid >> 5, lane = tid & 31;
    int wm = w >> 1, wn = w & 1;
    float4 c[2][4];
#pragma unroll
    for (int i = 0; i < 2; i++)
#pragma unroll
        for (int j = 0; j < 4; j++) c[i][j] = make_float4(0.f, 0.f, 0.f, 0.f);
    int arow = tid >> 1, akq = (tid & 1) * 16;
    int xm = min(m0 + arow, NPAR - 1);
    for (int kc = 0; kc < H; kc += 32) {
        const float* xr = g_xepar + (size_t)xm * H + kc + akq;
#pragma unroll
        for (int q = 0; q < 4; q++) {
            float4 v = *(const float4*)(xr + q * 4);
            float vv[4] = {v.x, v.y, v.z, v.w};
#pragma unroll
            for (int j = 0; j < 4; j++) {
                int o = arow * 36 + akq + q * 4 + j;
                unsigned h = f2tf(vv[j]);
                sAh[o] = __uint_as_float(h);
                sAl[o] = __uint_as_float(f2tf(vv[j] - __uint_as_float(h)));
            }
        }
        __syncthreads();
#pragma unroll
        for (int k8 = 0; k8 < 4; k8++) {
            unsigned ah[2][4], al[2][4];
#pragma unroll
            for (int mt = 0; mt < 2; mt++) {
                int ab = (wm * 32 + mt * 16 + (lane >> 2)) * 36 + k8 * 8 + (lane & 3);
                ah[mt][0] = fau(sAh[ab]);     ah[mt][1] = fau(sAh[ab + 288]);
                ah[mt][2] = fau(sAh[ab + 4]); ah[mt][3] = fau(sAh[ab + 292]);
                al[mt][0] = fau(sAl[ab]);     al[mt][1] = fau(sAl[ab + 288]);
                al[mt][2] = fau(sAl[ab + 4]); al[mt][3] = fau(sAl[ab + 292]);
            }
#pragma unroll
            for (int nt = 0; nt < 4; nt++) {
                size_t fo = (((size_t)mat * FR + (n0 >> 3) + wn * 4 + nt) * FR
                             + (kc >> 3) + k8) * 64 + lane * 2;
                uint2 bh2 = __ldg((const uint2*)&g_bfh[fo]);
                uint2 bl2 = __ldg((const uint2*)&g_bfl[fo]);
                mma3u(c[0][nt], ah[0], al[0], bh2, bl2);
                mma3u(c[1][nt], ah[1], al[1], bh2, bl2);
            }
        }
        __syncthreads();
    }
#pragma unroll
    for (int mt = 0; mt < 2; mt++)
#pragma unroll
    for (int nt = 0; nt < 4; nt++) {
        float vals[4] = {c[mt][nt].x, c[mt][nt].y, c[mt][nt].z, c[mt][nt].w};
#pragma unroll
        for (int rr = 0; rr < 2; rr++) {
            int m = m0 + (wm * 2 + mt) * 16 + (lane >> 2) + rr * 8;
            if (m >= NPAR) continue;
#pragma unroll
            for (int cc = 0; cc < 2; cc++) {
                int d = n0 + (wn * 4 + nt) * 8 + 2 * (lane & 3) + cc;
                out[(size_t)m * H + d] = vals[rr * 2 + cc] + bias[d];
            }
        }
    }
}

// ---------------- launch 5: persistent level-synchronous main ----------------
__device__ __forceinline__ void gridbar(int nb, int& sense) {
    __syncthreads();
    if (threadIdx.x == 0) {
        sense ^= 1;
        __threadfence();
        if (atomicAdd(&g_barcnt, 1) == nb - 1) {
            atomicExch(&g_barcnt, 0);
            __threadfence();
            g_barsense = sense;
        } else {
            while (g_barsense != sense) __nanosleep(32);
        }
        __threadfence();
    }
    __syncthreads();
}

#define AH(buf,k,head) (((buf)*4+(k))*8+(head))*65

__device__ int attn_core(int p, const int* __restrict__ tree, float* SBUF,
                         int* s_child, float* s_sc, float* s_p) {
    int tid = threadIdx.x;
    __syncthreads();
    if (tid < DEG) s_child[tid] = tree[p * DEG + tid];
    __syncthreads();
#pragma unroll
    for (int j = 0; j < 8; j++) {
        int idx = tid + j * 256;
        int k = idx >> 9, col = idx & 511, head = col >> 6, d = col & 63;
        int c = s_child[k];
        SBUF[AH(0, k, head) + d] = (c > -1) ? __ldcg(&g_nodeh[(size_t)c * H + col]) : 0.f;
    }
    __syncthreads();
    int cur = 0;
    for (int layer = 0; layer < NLAYER; layer++) {
        if (tid < 128) {
            int head = tid >> 4, q = (tid >> 2) & 3, kk = tid & 3;
            const float* hq = &SBUF[AH(cur, q, head)];
            const float* hk = &SBUF[AH(cur, kk, head)];
            float s = 0.f;
#pragma unroll
            for (int d = 0; d < DK; d++) s += hq[d] * hk[d];
            s *= 0.125f;
            if (s_child[kk] <= -1) s = -1e9f;
            s_sc[(head * 4 + q) * 4 + kk] = s;
        }
        __syncthreads();
        if (tid < 32) {
            int head = tid >> 2, q = tid & 3;
            const float* r = &s_sc[(head * 4 + q) * 4];
            float m = fmaxf(fmaxf(r[0], r[1]), fmaxf(r[2], r[3]));
            float e0 = __expf(r[0] - m), e1 = __expf(r[1] - m);
            float e2 = __expf(r[2] - m), e3 = __expf(r[3] - m);
            float inv = 1.f / (e0 + e1 + e2 + e3);
            float* pr = &s_p[(head * 4 + q) * 4];
            pr[0] = e0 * inv; pr[1] = e1 * inv; pr[2] = e2 * inv; pr[3] = e3 * inv;
        }
        __syncthreads();
        int nxt = cur ^ 1;
#pragma unroll
        for (int j = 0; j < 2; j++) {
            int col = tid + j * 256, head = col >> 6, d = col & 63;
            float v0 = SBUF[AH(cur, 0, head) + d];
            float v1 = SBUF[AH(cur, 1, head) + d];
            float v2 = SBUF[AH(cur, 2, head) + d];
            float v3 = SBUF[AH(cur, 3, head) + d];
#pragma unroll
            for (int q = 0; q < 4; q++) {
                const float* pr = &s_p[(head * 4 + q) * 4];
                SBUF[AH(nxt, q, head) + d] = pr[0] * v0 + pr[1] * v1 + pr[2] * v2 + pr[3] * v3;
            }
        }
        __syncthreads();
        cur = nxt;
    }
    return cur;
}

__device__ void phaseA(int row, const int* __restrict__ tree, float* SBUF,
                       int* s_child, float* s_sc, float* s_p) {
    int tid = threadIdx.x;
    int p = g_order[row];
    int cur = attn_core(p, tree, SBUF, s_child, s_sc, s_p);
    int cc = (s_child[0] > -1) + (s_child[1] > -1) + (s_child[2] > -1) + (s_child[3] > -1);
    float denom = (float)max(cc, 1);
#pragma unroll
    for (int j = 0; j < 2; j++) {
        int col = tid + j * 256, head = col >> 6, d = col & 63;
        float m = 0.f;
#pragma unroll
        for (int k = 0; k < DEG; k++)
            if (s_child[k] > -1) m += SBUF[AH(cur, k, head) + d];
        __stcg(&g_memv[(size_t)row * H + col], m / denom);
    }
}

// cooperative fp32 matvec path for tiny levels
__device__ void coopB(int start, int cnt, const float* __restrict__ Uz,
                      const float* __restrict__ Ur) {
    int gw = blockIdx.x * 8 + (threadIdx.x >> 5);
    int nw = gridDim.x * 8;
    int lane = threadIdx.x & 31;
    int ntask = cnt * H;
    for (int t = gw; t < ntask; t += nw) {
        int i = t >> 9, d = t & 511;
        int row = start + i;
        const float4* mv = (const float4*)&g_memv[(size_t)row * H];
        const float4* uz = (const float4*)(Uz + (size_t)d * H);
        const float4* ur = (const float4*)(Ur + (size_t)d * H);
        float az = 0.f, ar = 0.f;
#pragma unroll
        for (int j = 0; j < 4; j++) {
            float4 m = __ldcg(&mv[lane + j * 32]);
            float4 a = __ldg(&uz[lane + j * 32]);
            az += a.x * m.x + a.y * m.y + a.z * m.z + a.w * m.w;
            float4 b = __ldg(&ur[lane + j * 32]);
            ar += b.x * m.x + b.y * m.y + b.z * m.z + b.w * m.w;
        }
#pragma unroll
        for (int o = 16; o; o >>= 1) {
            az += __shfl_down_sync(0xffffffffu, az, o);
            ar += __shfl_down_sync(0xffffffffu, ar, o);
        }
        if (lane == 0) {
            int p = g_order[row];
            size_t rb = (size_t)row * H + d;
            float z = sigf(__ldcg(&g_gz0[(size_t)p * H + d]) + az);
            float r = sigf(__ldcg(&g_gr0[(size_t)p * H + d]) + ar);
            float mem = __ldcg(&g_memv[rb]);
            __stcg(&g_zv[rb], z);
            __stcg(&g_mrv[rb], mem * r);
        }
    }
}

__device__ void coopC(int start, int cnt, const float* __restrict__ Uh) {
    int gw = blockIdx.x * 8 + (threadIdx.x >> 5);
    int nw = gridDim.x * 8;
    int lane = threadIdx.x & 31;
    int ntask = cnt * H;
    for (int t = gw; t < ntask; t += nw) {
        int i = t >> 9, d = t & 511;
        int row = start + i;
        const float4* mrv = (const float4*)&g_mrv[(size_t)row * H];
        const float4* uh = (const float4*)(Uh + (size_t)d * H);
        float ah = 0.f;
#pragma unroll
        for (int j = 0; j < 4; j++) {
            float4 m = __ldcg(&mrv[lane + j * 32]);
            float4 a = __ldg(&uh[lane + j * 32]);
            ah += a.x * m.x + a.y * m.y + a.z * m.z + a.w * m.w;
        }
#pragma unroll
        for (int o = 16; o; o >>= 1) ah += __shfl_down_sync(0xffffffffu, ah, o);
        if (lane == 0) {
            int p = g_order[row];
            size_t rb = (size_t)row * H + d;
            float c = tanhf(__ldcg(&g_gh0[(size_t)p * H + d]) + ah);
            float z = __ldcg(&g_zv[rb]);
            float mem = __ldcg(&g_memv[rb]);
            __stcg(&g_nodeh[(size_t)(NLEAF + p) * H + d], z * mem + (1.f - z) * c);
        }
    }
}

// phaseB: BM=32, BN=64; Uz(mat3)+Ur(mat4); B from gmem frags
__device__ void phaseB(int start, int cnt, int t, float* SBUF, int* s_pid) {
    int tid = threadIdx.x;
    int m0 = (t >> 3) * 32, n0 = (t & 7) * 64;
    float* sAh = SBUF;            // 32*36
    float* sAl = SBUF + 1152;
    int w = tid >> 5, lane = tid & 31;
    int mat = w >> 2, ntb = (w & 3) * 2;
    float4 c[2][2];
#pragma unroll
    for (int i = 0; i < 2; i++)
#pragma unroll
        for (int j = 0; j < 2; j++) c[i][j] = make_float4(0.f, 0.f, 0.f, 0.f);
    __syncthreads();
    if (tid < 32) s_pid[tid] = g_order[start + min(m0 + tid, cnt - 1)];
    int arow = tid >> 3, ak = (tid & 7) * 4;
    int rrow = start + min(m0 + arow, cnt - 1);
    for (int kc = 0; kc < H; kc += 32) {
        float4 a = __ldcg((const float4*)&g_memv[(size_t)rrow * H + kc + ak]);
        float av[4] = {a.x, a.y, a.z, a.w};
#pragma unroll
        for (int j = 0; j < 4; j++) {
            int o = arow * 36 + ak + j;
            unsigned h = f2tf(av[j]);
            sAh[o] = __uint_as_float(h);
            sAl[o] = __uint_as_float(f2tf(av[j] - __uint_as_float(h)));
        }
        __syncthreads();
#pragma unroll
        for (int k8 = 0; k8 < 4; k8++) {
            unsigned ah[2][4], al[2][4];
#pragma unroll
            for (int mt = 0; mt < 2; mt++) {
                int ab = (mt * 16 + (lane >> 2)) * 36 + k8 * 8 + (lane & 3);
                ah[mt][0] = fau(sAh[ab]);     ah[mt][1] = fau(sAh[ab + 288]);
                ah[mt][2] = fau(sAh[ab + 4]); ah[mt][3] = fau(sAh[ab + 292]);
                al[mt][0] = fau(sAl[ab]);     al[mt][1] = fau(sAl[ab + 288]);
                al[mt][2] = fau(sAl[ab + 4]); al[mt][3] = fau(sAl[ab + 292]);
            }
#pragma unroll
            for (int nt2 = 0; nt2 < 2; nt2++) {
                size_t fo = (((size_t)(3 + mat) * FR + (n0 >> 3) + ntb + nt2) * FR
                             + (kc >> 3) + k8) * 64 + lane * 2;
                uint2 bh2 = __ldg((const uint2*)&g_bfh[fo]);
                uint2 bl2 = __ldg((const uint2*)&g_bfl[fo]);
                mma3u(c[0][nt2], ah[0], al[0], bh2, bl2);
                mma3u(c[1][nt2], ah[1], al[1], bh2, bl2);
            }
        }
        __syncthreads();
    }
#pragma unroll
    for (int mt = 0; mt < 2; mt++)
#pragma unroll
    for (int nt2 = 0; nt2 < 2; nt2++) {
        float vals[4] = {c[mt][nt2].x, c[mt][nt2].y, c[mt][nt2].z, c[mt][nt2].w};
#pragma unroll
        for (int rr = 0; rr < 2; rr++) {
            int rl = mt * 16 + (lane >> 2) + rr * 8;
            if (m0 + rl >= cnt) continue;
            int p = s_pid[rl];
#pragma unroll
            for (int cc2 = 0; cc2 < 2; cc2++) {
                int d = n0 + (ntb + nt2) * 8 + 2 * (lane & 3) + cc2;
                size_t rb = (size_t)(start + m0 + rl) * H + d;
                size_t pb = (size_t)p * H + d;
                float acc = vals[rr * 2 + cc2];
                if (mat == 0) {
                    __stcg(&g_zv[rb], sigf(__ldcg(&g_gz0[pb]) + acc));
                } else {
                    float r = sigf(__ldcg(&g_gr0[pb]) + acc);
                    __stcg(&g_mrv[rb], __ldcg(&g_memv[rb]) * r);
                }
            }
        }
    }
}

// phaseC: BM=32, BN=128, Uh(mat5); B from gmem frags
__device__ void phaseC(int start, int cnt, int t, float* SBUF, int* s_pid) {
    int tid = threadIdx.x;
    int m0 = (t >> 2) * 32, n0 = (t & 3) * 128;
    float* sAh = SBUF;
    float* sAl = SBUF + 1152;
    int w = tid >> 5, lane = tid & 31;
    int ntb = w * 2;
    float4 c[2][2];
#pragma unroll
    for (int i = 0; i < 2; i++)
#pragma unroll
        for (int j = 0; j < 2; j++) c[i][j] = make_float4(0.f, 0.f, 0.f, 0.f);
    __syncthreads();
    if (tid < 32) s_pid[tid] = g_order[start + min(m0 + tid, cnt - 1)];
    int arow = tid >> 3, ak = (tid & 7) * 4;
    int rrow = start + min(m0 + arow, cnt - 1);
    for (int kc = 0; kc < H; kc += 32) {
        float4 a = __ldcg((const float4*)&g_mrv[(size_t)rrow * H + kc + ak]);
        float av[4] = {a.x, a.y, a.z, a.w};
#pragma unroll
        for (int j = 0; j < 4; j++) {
            int o = arow * 36 + ak + j;
            unsigned h = f2tf(av[j]);
            sAh[o] = __uint_as_float(h);
            sAl[o] = __uint_as_float(f2tf(av[j] - __uint_as_float(h)));
        }
        __syncthreads();
#pragma unroll
        for (int k8 = 0; k8 < 4; k8++) {
            unsigned ah[2][4], al[2][4];
#pragma unroll
            for (int mt = 0; mt < 2; mt++) {
                int ab = (mt * 16 + (lane >> 2)) * 36 + k8 * 8 + (lane & 3);
                ah[mt][0] = fau(sAh[ab]);     ah[mt][1] = fau(sAh[ab + 288]);
                ah[mt][2] = fau(sAh[ab + 4]); ah[mt][3] = fau(sAh[ab + 292]);
                al[mt][0] = fau(sAl[ab]);     al[mt][1] = fau(sAl[ab + 288]);
                al[mt][2] = fau(sAl[ab + 4]); al[mt][3] = fau(sAl[ab + 292]);
            }
#pragma unroll
            for (int nt2 = 0; nt2 < 2; nt2++) {
                size_t fo = (((size_t)5 * FR + (n0 >> 3) + ntb + nt2) * FR
                             + (kc >> 3) + k8) * 64 + lane * 2;
                uint2 bh2 = __ldg((const uint2*)&g_bfh[fo]);
                uint2 bl2 = __ldg((const uint2*)&g_bfl[fo]);
                mma3u(c[0][nt2], ah[0], al[0], bh2, bl2);
                mma3u(c[1][nt2], ah[1], al[1], bh2, bl2);
            }
        }
        __syncthreads();
    }
#pragma unroll
    for (int mt = 0; mt < 2; mt++)
#pragma unroll
    for (int nt2 = 0; nt2 < 2; nt2++) {
        float vals[4] = {c[mt][nt2].x, c[mt][nt2].y, c[mt][nt2].z, c[mt][nt2].w};
#pragma unroll
        for (int rr = 0; rr < 2; rr++) {
            int rl = mt * 16 + (lane >> 2) + rr * 8;
            if (m0 + rl >= cnt) continue;
            int p = s_pid[rl];
#pragma unroll
            for (int cc2 = 0; cc2 < 2; cc2++) {
                int d = n0 + (ntb + nt2) * 8 + 2 * (lane & 3) + cc2;
                size_t rb = (size_t)(start + m0 + rl) * H + d;
                size_t pb = (size_t)p * H + d;
                float cval = tanhf(__ldcg(&g_gh0[pb]) + vals[rr * 2 + cc2]);
                float z = __ldcg(&g_zv[rb]);
                float mem = __ldcg(&g_memv[rb]);
                __stcg(&g_nodeh[(size_t)(NLEAF + p) * H + d], z * mem + (1.f - z) * cval);
            }
        }
    }
}

__global__ void __launch_bounds__(256) k_main(
    const int* __restrict__ tree,
    const float* __restrict__ Uz, const float* __restrict__ Ur,
    const float* __restrict__ Uh)
{
    __shared__ float SBUF[4608];
    __shared__ float s_sc[128], s_p[128];
    __shared__ int s_child[DEG], s_pid[32];
    int nb = gridDim.x;
    int sense = 0;
    int tid = threadIdx.x;
    int gstride = nb * 256;

    // ---- leveling prologue ----
    for (int p = blockIdx.x * 256 + tid; p < NPAR; p += gstride) {
        int lv = 0;
#pragma unroll
        for (int k = 0; k < DEG; k++) {
            int c = tree[p * DEG + k];
            if (c >= NLEAF) {
                int v;
                while ((v = atomicAdd(&g_lvl[c - NLEAF], 0)) < 0) __nanosleep(40);
                lv = max(lv, v + 1);
            }
        }
        if (lv > LMAX - 1) lv = LMAX - 1;
        atomicExch(&g_lvl[p], lv);
    }
    gridbar(nb, sense);
    for (int p = blockIdx.x * 256 + tid; p < NPAR; p += gstride)
        atomicAdd(&g_hist[g_lvl[p]], 1);
    gridbar(nb, sense);
    if (blockIdx.x == 0 && tid == 0) {
        int acc = 0, nl = 1;
        for (int i = 0; i < LMAX; i++) {
            g_lstart[i] = acc; g_lofs[i] = acc;
            acc += g_hist[i];
            if (g_hist[i] > 0) nl = i + 1;
        }
        g_nlev = nl;
    }
    gridbar(nb, sense);
    for (int p = blockIdx.x * 256 + tid; p < NPAR; p += gstride)
        g_order[atomicAdd(&g_lofs[g_lvl[p]], 1)] = p;
    gridbar(nb, sense);

    int nlev = g_nlev;
    for (int l = 0; l < nlev; l++) {
        int start = g_lstart[l], cnt = g_hist[l];
        if (cnt == 0) continue;
        for (int j = blockIdx.x; j < cnt; j += nb)
            phaseA(start + j, tree, SBUF, s_child, s_sc, s_p);
        gridbar(nb, sense);
        if (cnt < 32) {
            coopB(start, cnt, Uz, Ur);
            gridbar(nb, sense);
            coopC(start, cnt, Uh);
            gridbar(nb, sense);
        } else {
            int mt = (cnt + 31) >> 5;
            int ntB = mt * 8;
            for (int t = blockIdx.x; t < ntB; t += nb)
                phaseB(start, cnt, t, SBUF, s_pid);
            gridbar(nb, sense);
            int ntC = mt * 4;
            for (int t = blockIdx.x; t < ntC; t += nb)
                phaseC(start, cnt, t, SBUF, s_pid);
            gridbar(nb, sense);
        }
    }
}

// ---------------- reductions ----------------
__global__ void k_redmax() {
    int tid = threadIdx.x;
    int b = blockIdx.x;
    const float* base = g_nodeh + (size_t)NLEAF * H;
    float m = -3.4e38f;
    for (int p = b * RED_CHUNK; p < (b + 1) * RED_CHUNK; p++)
        m = fmaxf(m, base[(size_t)p * H + tid]);
    g_pmax[b * H + tid] = m;
}

__global__ void k_final(const float* __restrict__ Wo, const float* __restrict__ bo,
                        float* __restrict__ out) {
    __shared__ float s_f[H];
    __shared__ float s_logit[NCLASS];
    int tid = threadIdx.x;   // 512
    float m = g_pmax[tid];
    for (int b = 1; b < NB_RED; b++) m = fmaxf(m, g_pmax[b * H + tid]);
    s_f[tid] = m;
    __syncthreads();
    int w = tid >> 5, lane = tid & 31;
    if (w < NCLASS) {
        float acc = 0.f;
        for (int j = lane; j < H; j += 32) acc += Wo[w * H + j] * s_f[j];
#pragma unroll
        for (int o = 16; o; o >>= 1) acc += __shfl_down_sync(0xffffffffu, acc, o);
        if (lane == 0) s_logit[w] = acc + bo[w];
    }
    __syncthreads();
    if (tid == 0) {
        float mx = s_logit[0];
        for (int i = 1; i < NCLASS; i++) mx = fmaxf(mx, s_logit[i]);
        float e[NCLASS], s = 0.f;
        for (int i = 0; i < NCLASS; i++) { e[i] = __expf(s_logit[i] - mx); s += e[i]; }
        for (int i = 0; i < NCLASS; i++) out[i] = e[i] / s;
    }
}

extern "C" void kernel_launch(void* const* d_in, const int* in_sizes, int n_in,
                              void* d_out, int out_size) {
    const float* x_word  = (const float*)d_in[0];
    const int*   x_index = (const int*)  d_in[1];
    const int*   tree    = (const int*)  d_in[2];
    const float* E_bu    = (const float*)d_in[3];
    const float* W_z = (const float*)d_in[4];
    const float* U_z = (const float*)d_in[5];
    const float* b_z = (const float*)d_in[6];
    const float* W_r = (const float*)d_in[7];
    const float* U_r = (const float*)d_in[8];
    const float* b_r = (const float*)d_in[9];
    const float* W_h = (const float*)d_in[10];
    const float* U_h = (const float*)d_in[11];
    const float* b_h = (const float*)d_in[12];
    const float* W_out = (const float*)d_in[13];
    const float* b_out = (const float*)d_in[14];
    float* out = (float*)d_out;

    static int nb_main = 0;
    if (nb_main == 0) {
        int dev = 0; cudaGetDevice(&dev);
        int nsm = 0; cudaDeviceGetAttribute(&nsm, cudaDevAttrMultiProcessorCount, dev);
        int perSM = 0;
        cudaOccupancyMaxActiveBlocksPerMultiprocessor(&perSM, k_main, 256, 0);
        if (perSM < 1) perSM = 1;
        nb_main = nsm * perSM;
    }

    dim3 tb(32, 8), tg((VOCAB + 31) / 32, H / 32);
    k_setup<<<tg, tb>>>(E_bu);
    k_split<<<(6 * FR * FR * 32 + 255) / 256, 256>>>(W_z, W_r, W_h, U_z, U_r, U_h);
    k_embed<<<NTOT, 128>>>(x_word, x_index);
    k_pregemm<<<dim3((NPAR + 127) / 128, H / 64, 3), 256>>>(b_z, b_r, b_h);
    k_main<<<nb_main, 256>>>(tree, U_z, U_r, U_h);
    k_redmax<<<NB_RED, H>>>();
    k_final<<<1, H>>>(W_out, b_out, out);
}

// round 16
// speedup vs baseline: 1.5366x; 1.0272x over previous
#include <cuda_runtime.h>
#include <cstdint>

#define H 512
#define DK 64
#define NCLASS 4
#define VOCAB 5000
#define LW 32
#define NLEAF 20000
#define NPAR 20000
#define NTOT 40000
#define DEG 4
#define NLAYER 5
#define LMAX 256
#define GMAX 2048
#define NB_RED 125
#define RED_CHUNK 160
#define FR 64   // H/8 fragment tiles

__device__ float g_nodeh[(size_t)NTOT * H];
__device__ float g_xepar[(size_t)NPAR * H];
__device__ float g_EbuT[(size_t)VOCAB * H];
__device__ float g_gz0[(size_t)NPAR * H];
__device__ float g_gr0[(size_t)NPAR * H];
__device__ float g_gh0[(size_t)NPAR * H];
__device__ float g_memv[(size_t)NPAR * H];
__device__ float g_mrv[(size_t)NPAR * H];
__device__ float g_zv[(size_t)NPAR * H];
__device__ unsigned g_bfh[(size_t)6 * FR * FR * 64];
__device__ unsigned g_bfl[(size_t)6 * FR * FR * 64];
__device__ int g_lvl[NPAR];
__device__ int g_hist[LMAX], g_lstart[LMAX], g_lofs[LMAX], g_order[NPAR];
__device__ int g_gbase[LMAX];
__device__ int g_acnt[GMAX], g_bcnt[GMAX];
__device__ int g_nlev, g_barcnt;
__device__ volatile int g_barsense;
__device__ float g_pmax[NB_RED * H];

__device__ __forceinline__ float sigf(float x) { return 1.f / (1.f + __expf(-x)); }

__device__ __forceinline__ unsigned f2tf(float x) {
    unsigned u; asm("cvt.rna.tf32.f32 %0, %1;" : "=r"(u) : "f"(x)); return u;
}
__device__ __forceinline__ void mma8(float4& d,
    unsigned a0, unsigned a1, unsigned a2, unsigned a3, unsigned b0, unsigned b1) {
    asm("mma.sync.aligned.m16n8k8.row.col.f32.tf32.tf32.f32 "
        "{%0,%1,%2,%3},{%4,%5,%6,%7},{%8,%9},{%0,%1,%2,%3};"
        : "+f"(d.x), "+f"(d.y), "+f"(d.z), "+f"(d.w)
        : "r"(a0), "r"(a1), "r"(a2), "r"(a3), "r"(b0), "r"(b1));
}
__device__ __forceinline__ unsigned fau(float x) { return __float_as_uint(x); }
__device__ __forceinline__ void mma3u(float4& c, const unsigned* ah, const unsigned* al,
                                      uint2 bh, uint2 bl) {
    mma8(c, ah[0], ah[1], ah[2], ah[3], bh.x, bh.y);
    mma8(c, ah[0], ah[1], ah[2], ah[3], bl.x, bl.y);
    mma8(c, al[0], al[1], al[2], al[3], bh.x, bh.y);
}
__device__ __forceinline__ void waitcnt(int* cnt, int target) {
    while (atomicAdd(cnt, 0) < target) __nanosleep(60);
    __threadfence();
}

// ---------------- launch 1: transpose + init ----------------
__global__ void k_setup(const float* __restrict__ E) {
    __shared__ float t[32][33];
    int x = blockIdx.x * 32 + threadIdx.x;
    int y0 = blockIdx.y * 32;
#pragma unroll
    for (int j = 0; j < 32; j += 8) {
        int y = y0 + threadIdx.y + j;
        t[threadIdx.y + j][threadIdx.x] = (x < VOCAB) ? E[(size_t)y * VOCAB + x] : 0.f;
    }
    __syncthreads();
    int xo = blockIdx.y * 32 + threadIdx.x;
    int yo0 = blockIdx.x * 32;
#pragma unroll
    for (int j = 0; j < 32; j += 8) {
        int yo = yo0 + threadIdx.y + j;
        if (yo < VOCAB) g_EbuT[(size_t)yo * H + xo] = t[threadIdx.x][threadIdx.y + j];
    }
    if (blockIdx.x == 0 && blockIdx.y == 0) {
        int tid = threadIdx.y * 32 + threadIdx.x;
        for (int i = tid; i < NPAR; i += 256) g_lvl[i] = -1;
        for (int i = tid; i < GMAX; i += 256) { g_acnt[i] = 0; g_bcnt[i] = 0; }
        if (tid < LMAX) g_hist[tid] = 0;
        if (tid == 0) { g_barcnt = 0; g_barsense = 0; }
    }
}

// ---------------- launch 2: split weights into fragment-order tf32 hi/lo ----------------
__global__ void k_split(const float* __restrict__ Wz, const float* __restrict__ Wr,
                        const float* __restrict__ Wh, const float* __restrict__ Uz,
                        const float* __restrict__ Ur, const float* __restrict__ Uh) {
    int idx = blockIdx.x * 256 + threadIdx.x;
    if (idx >= 6 * FR * FR * 32) return;
    int lane = idx & 31;
    int k8 = (idx >> 5) & 63;
    int nt = (idx >> 11) & 63;
    int mat = idx >> 17;
    const float* src = mat == 0 ? Wz : mat == 1 ? Wr : mat == 2 ? Wh
                     : mat == 3 ? Uz : mat == 4 ? Ur : Uh;
    int n = nt * 8 + (lane >> 2);
    int k = k8 * 8 + (lane & 3);
    float x0 = src[(size_t)n * H + k];
    float x1 = src[(size_t)n * H + k + 4];
    unsigned h0 = f2tf(x0), h1 = f2tf(x1);
    size_t o = (size_t)idx * 2;
    g_bfh[o] = h0; g_bfh[o + 1] = h1;
    g_bfl[o] = f2tf(x0 - __uint_as_float(h0));
    g_bfl[o + 1] = f2tf(x1 - __uint_as_float(h1));
}

// ---------------- launch 3: embed ----------------
__global__ void k_embed(const float* __restrict__ xw, const int* __restrict__ xi) {
    int n = blockIdx.x;
    int tid = threadIdx.x;   // 128
    __shared__ float s_w[LW];
    __shared__ int   s_i[LW];
    if (tid < LW) { s_w[tid] = xw[n * LW + tid]; s_i[tid] = xi[n * LW + tid]; }
    __syncthreads();
    float4 acc = make_float4(0.f, 0.f, 0.f, 0.f);
#pragma unroll 8
    for (int l = 0; l < LW; l++) {
        float4 e = ((const float4*)(g_EbuT + (size_t)s_i[l] * H))[tid];
        float w = s_w[l];
        acc.x += w * e.x; acc.y += w * e.y; acc.z += w * e.z; acc.w += w * e.w;
    }
    float4* dst = (n < NLEAF) ? (float4*)(g_nodeh + (size_t)n * H)
                              : (float4*)(g_xepar + (size_t)(n - NLEAF) * H);
    dst[tid] = acc;
}

// ---------------- launch 4: pre-GEMM ----------------
__global__ void __launch_bounds__(256, 3) k_pregemm(
    const float* __restrict__ bz, const float* __restrict__ br, const float* __restrict__ bh)
{
    __shared__ float SM[9216];
    float* sAh = SM;
    float* sAl = SM + 4608;
    int mat = blockIdx.z;
    const float* bias = mat == 0 ? bz : mat == 1 ? br : bh;
    float* out = mat == 0 ? g_gz0 : mat == 1 ? g_gr0 : g_gh0;
    int m0 = blockIdx.x * 128, n0 = blockIdx.y * 64;
    int tid = threadIdx.x;
    int w = tid >> 5, lane = tid & 31;
    int wm = w >> 1, wn = w & 1;
    float4 c[2][4];
#pragma unroll
    for (int i = 0; i < 2; i++)
#pragma unroll
        for (int j = 0; j < 4; j++) c[i][j] = make_float4(0.f, 0.f, 0.f, 0.f);
    int arow = tid >> 1, akq = (tid & 1) * 16;
    int xm = min(m0 + arow, NPAR - 1);
    for (int kc = 0; kc < H; kc += 32) {
        const float* xr = g_xepar + (size_t)xm * H + kc + akq;
#pragma unroll
        for (int q = 0; q < 4; q++) {
            float4 v = *(const float4*)(xr + q * 4);
            float vv[4] = {v.x, v.y, v.z, v.w};
#pragma unroll
            for (int j = 0; j < 4; j++) {
                int o = arow * 36 + akq + q * 4 + j;
                unsigned h = f2tf(vv[j]);
                sAh[o] = __uint_as_float(h);
                sAl[o] = __uint_as_float(f2tf(vv[j] - __uint_as_float(h)));
            }
        }
        __syncthreads();
#pragma unroll
        for (int k8 = 0; k8 < 4; k8++) {
            unsigned ah[2][4], al[2][4];
#pragma unroll
            for (int mt = 0; mt < 2; mt++) {
                int ab = (wm * 32 + mt * 16 + (lane >> 2)) * 36 + k8 * 8 + (lane & 3);
                ah[mt][0] = fau(sAh[ab]);     ah[mt][1] = fau(sAh[ab + 288]);
                ah[mt][2] = fau(sAh[ab + 4]); ah[mt][3] = fau(sAh[ab + 292]);
                al[mt][0] = fau(sAl[ab]);     al[mt][1] = fau(sAl[ab + 288]);
                al[mt][2] = fau(sAl[ab + 4]); al[mt][3] = fau(sAl[ab + 292]);
            }
#pragma unroll
            for (int nt = 0; nt < 4; nt++) {
                size_t fo = (((size_t)mat * FR + (n0 >> 3) + wn * 4 + nt) * FR
                             + (kc >> 3) + k8) * 64 + lane * 2;
                uint2 bh2 = __ldg((const uint2*)&g_bfh[fo]);
                uint2 bl2 = __ldg((const uint2*)&g_bfl[fo]);
                mma3u(c[0][nt], ah[0], al[0], bh2, bl2);
                mma3u(c[1][nt], ah[1], al[1], bh2, bl2);
            }
        }
        __syncthreads();
    }
#pragma unroll
    for (int mt = 0; mt < 2; mt++)
#pragma unroll
    for (int nt = 0; nt < 4; nt++) {
        float vals[4] = {c[mt][nt].x, c[mt][nt].y, c[mt][nt].z, c[mt][nt].w};
#pragma unroll
        for (int rr = 0; rr < 2; rr++) {
            int m = m0 + (wm * 2 + mt) * 16 + (lane >> 2) + rr * 8;
            if (m >= NPAR) continue;
#pragma unroll
            for (int cc = 0; cc < 2; cc++) {
                int d = n0 + (wn * 4 + nt) * 8 + 2 * (lane & 3) + cc;
                out[(size_t)m * H + d] = vals[rr * 2 + cc] + bias[d];
            }
        }
    }
}

// ---------------- launch 5: persistent main (counter-sync phases) ----------------
__device__ __forceinline__ void gridbar(int nb, int& sense) {
    __syncthreads();
    if (threadIdx.x == 0) {
        sense ^= 1;
        __threadfence();
        if (atomicAdd(&g_barcnt, 1) == nb - 1) {
            atomicExch(&g_barcnt, 0);
            __threadfence();
            g_barsense = sense;
        } else {
            while (g_barsense != sense) __nanosleep(32);
        }
        __threadfence();
    }
    __syncthreads();
}

#define AH(buf,k,head) (((buf)*4+(k))*8+(head))*65

__device__ int attn_core(int p, const int* __restrict__ tree, float* SBUF,
                         int* s_child, float* s_sc, float* s_p) {
    int tid = threadIdx.x;
    __syncthreads();
    if (tid < DEG) s_child[tid] = tree[p * DEG + tid];
    __syncthreads();
#pragma unroll
    for (int j = 0; j < 8; j++) {
        int idx = tid + j * 256;
        int k = idx >> 9, col = idx & 511, head = col >> 6, d = col & 63;
        int c = s_child[k];
        SBUF[AH(0, k, head) + d] = (c > -1) ? __ldcg(&g_nodeh[(size_t)c * H + col]) : 0.f;
    }
    __syncthreads();
    int cur = 0;
    for (int layer = 0; layer < NLAYER; layer++) {
        if (tid < 128) {
            int head = tid >> 4, q = (tid >> 2) & 3, kk = tid & 3;
            const float* hq = &SBUF[AH(cur, q, head)];
            const float* hk = &SBUF[AH(cur, kk, head)];
            float s = 0.f;
#pragma unroll
            for (int d = 0; d < DK; d++) s += hq[d] * hk[d];
            s *= 0.125f;
            if (s_child[kk] <= -1) s = -1e9f;
            s_sc[(head * 4 + q) * 4 + kk] = s;
        }
        __syncthreads();
        if (tid < 32) {
            int head = tid >> 2, q = tid & 3;
            const float* r = &s_sc[(head * 4 + q) * 4];
            float m = fmaxf(fmaxf(r[0], r[1]), fmaxf(r[2], r[3]));
            float e0 = __expf(r[0] - m), e1 = __expf(r[1] - m);
            float e2 = __expf(r[2] - m), e3 = __expf(r[3] - m);
            float inv = 1.f / (e0 + e1 + e2 + e3);
            float* pr = &s_p[(head * 4 + q) * 4];
            pr[0] = e0 * inv; pr[1] = e1 * inv; pr[2] = e2 * inv; pr[3] = e3 * inv;
        }
        __syncthreads();
        int nxt = cur ^ 1;
#pragma unroll
        for (int j = 0; j < 2; j++) {
            int col = tid + j * 256, head = col >> 6, d = col & 63;
            float v0 = SBUF[AH(cur, 0, head) + d];
            float v1 = SBUF[AH(cur, 1, head) + d];
            float v2 = SBUF[AH(cur, 2, head) + d];
            float v3 = SBUF[AH(cur, 3, head) + d];
#pragma unroll
            for (int q = 0; q < 4; q++) {
                const float* pr = &s_p[(head * 4 + q) * 4];
                SBUF[AH(nxt, q, head) + d] = pr[0] * v0 + pr[1] * v1 + pr[2] * v2 + pr[3] * v3;
            }
        }
        __syncthreads();
        cur = nxt;
    }
    return cur;
}

// phaseA: attention + mem; signals acnt for its group
__device__ void phaseA(int row, int start, int gbase, const int* __restrict__ tree,
                       float* SBUF, int* s_child, float* s_sc, float* s_p) {
    int tid = threadIdx.x;
    int p = g_order[row];
    int cur = attn_core(p, tree, SBUF, s_child, s_sc, s_p);
    int cc = (s_child[0] > -1) + (s_child[1] > -1) + (s_child[2] > -1) + (s_child[3] > -1);
    float denom = (float)max(cc, 1);
#pragma unroll
    for (int j = 0; j < 2; j++) {
        int col = tid + j * 256, head = col >> 6, d = col & 63;
        float m = 0.f;
#pragma unroll
        for (int k = 0; k < DEG; k++)
            if (s_child[k] > -1) m += SBUF[AH(cur, k, head) + d];
        __stcg(&g_memv[(size_t)row * H + col], m / denom);
    }
    __syncthreads();
    if (tid == 0) {
        __threadfence();
        atomicAdd(&g_acnt[gbase + (row - start) / 32], 1);
    }
}

// cooperative fp32 matvec path for tiny levels (counter-synced)
__device__ void coopB(int start, int cnt, int g, const float* __restrict__ Uz,
                      const float* __restrict__ Ur) {
    int gw = blockIdx.x * 8 + (threadIdx.x >> 5);
    int nw = gridDim.x * 8;
    int lane = threadIdx.x & 31;
    int ntask = cnt * H;
    for (int t = gw; t < ntask; t += nw) {
        if (lane == 0) waitcnt(&g_acnt[g], cnt);
        __syncwarp();
        int i = t >> 9, d = t & 511;
        int row = start + i;
        const float4* mv = (const float4*)&g_memv[(size_t)row * H];
        const float4* uz = (const float4*)(Uz + (size_t)d * H);
        const float4* ur = (const float4*)(Ur + (size_t)d * H);
        float az = 0.f, ar = 0.f;
#pragma unroll
        for (int j = 0; j < 4; j++) {
            float4 m = __ldcg(&mv[lane + j * 32]);
            float4 a = __ldg(&uz[lane + j * 32]);
            az += a.x * m.x + a.y * m.y + a.z * m.z + a.w * m.w;
            float4 b = __ldg(&ur[lane + j * 32]);
            ar += b.x * m.x + b.y * m.y + b.z * m.z + b.w * m.w;
        }
#pragma unroll
        for (int o = 16; o; o >>= 1) {
            az += __shfl_down_sync(0xffffffffu, az, o);
            ar += __shfl_down_sync(0xffffffffu, ar, o);
        }
        if (lane == 0) {
            int p = g_order[row];
            size_t rb = (size_t)row * H + d;
            float z = sigf(__ldcg(&g_gz0[(size_t)p * H + d]) + az);
            float r = sigf(__ldcg(&g_gr0[(size_t)p * H + d]) + ar);
            float mem = __ldcg(&g_memv[rb]);
            __stcg(&g_zv[rb], z);
            __stcg(&g_mrv[rb], mem * r);
            __threadfence();
            atomicAdd(&g_bcnt[g], 1);
        }
    }
}

__device__ void coopC(int start, int cnt, int g, const float* __restrict__ Uh) {
    int gw = blockIdx.x * 8 + (threadIdx.x >> 5);
    int nw = gridDim.x * 8;
    int lane = threadIdx.x & 31;
    int ntask = cnt * H;
    for (int t = gw; t < ntask; t += nw) {
        if (lane == 0) waitcnt(&g_bcnt[g], ntask);
        __syncwarp();
        int i = t >> 9, d = t & 511;
        int row = start + i;
        const float4* mrv = (const float4*)&g_mrv[(size_t)row * H];
        const float4* uh = (const float4*)(Uh + (size_t)d * H);
        float ah = 0.f;
#pragma unroll
        for (int j = 0; j < 4; j++) {
            float4 m = __ldcg(&mrv[lane + j * 32]);
            float4 a = __ldg(&uh[lane + j * 32]);
            ah += a.x * m.x + a.y * m.y + a.z * m.z + a.w * m.w;
        }
#pragma unroll
        for (int o = 16; o; o >>= 1) ah += __shfl_down_sync(0xffffffffu, ah, o);
        if (lane == 0) {
            int p = g_order[row];
            size_t rb = (size_t)row * H + d;
            float c = tanhf(__ldcg(&g_gh0[(size_t)p * H + d]) + ah);
            float z = __ldcg(&g_zv[rb]);
            float mem = __ldcg(&g_memv[rb]);
            __stcg(&g_nodeh[(size_t)(NLEAF + p) * H + d], z * mem + (1.f - z) * c);
        }
    }
}

// phaseB: BM=32, BN=64; waits acnt==gsz, signals bcnt
__device__ void phaseB(int start, int cnt, int gbase, int t, float* SBUF, int* s_pid) {
    int tid = threadIdx.x;
    int m0 = (t >> 3) * 32, n0 = (t & 7) * 64;
    int g = gbase + (m0 >> 5);
    int gsz = min(32, cnt - m0);
    float* sAh = SBUF;
    float* sAl = SBUF + 1152;
    int w = tid >> 5, lane = tid & 31;
    int mat = w >> 2, ntb = (w & 3) * 2;
    float4 c[2][2];
#pragma unroll
    for (int i = 0; i < 2; i++)
#pragma unroll
        for (int j = 0; j < 2; j++) c[i][j] = make_float4(0.f, 0.f, 0.f, 0.f);
    __syncthreads();
    if (tid == 0) waitcnt(&g_acnt[g], gsz);
    __syncthreads();
    if (tid < 32) s_pid[tid] = g_order[start + min(m0 + tid, cnt - 1)];
    int arow = tid >> 3, ak = (tid & 7) * 4;
    int rrow = start + min(m0 + arow, cnt - 1);
    for (int kc = 0; kc < H; kc += 32) {
        float4 a = __ldcg((const float4*)&g_memv[(size_t)rrow * H + kc + ak]);
        float av[4] = {a.x, a.y, a.z, a.w};
#pragma unroll
        for (int j = 0; j < 4; j++) {
            int o = arow * 36 + ak + j;
            unsigned h = f2tf(av[j]);
            sAh[o] = __uint_as_float(h);
            sAl[o] = __uint_as_float(f2tf(av[j] - __uint_as_float(h)));
        }
        __syncthreads();
#pragma unroll
        for (int k8 = 0; k8 < 4; k8++) {
            unsigned ah[2][4], al[2][4];
#pragma unroll
            for (int mt = 0; mt < 2; mt++) {
                int ab = (mt * 16 + (lane >> 2)) * 36 + k8 * 8 + (lane & 3);
                ah[mt][0] = fau(sAh[ab]);     ah[mt][1] = fau(sAh[ab + 288]);
                ah[mt][2] = fau(sAh[ab + 4]); ah[mt][3] = fau(sAh[ab + 292]);
                al[mt][0] = fau(sAl[ab]);     al[mt][1] = fau(sAl[ab + 288]);
                al[mt][2] = fau(sAl[ab + 4]); al[mt][3] = fau(sAl[ab + 292]);
            }
#pragma unroll
            for (int nt2 = 0; nt2 < 2; nt2++) {
                size_t fo = (((size_t)(3 + mat) * FR + (n0 >> 3) + ntb + nt2) * FR
                             + (kc >> 3) + k8) * 64 + lane * 2;
                uint2 bh2 = __ldg((const uint2*)&g_bfh[fo]);
                uint2 bl2 = __ldg((const uint2*)&g_bfl[fo]);
                mma3u(c[0][nt2], ah[0], al[0], bh2, bl2);
                mma3u(c[1][nt2], ah[1], al[1], bh2, bl2);
            }
        }
        __syncthreads();
    }
#pragma unroll
    for (int mt = 0; mt < 2; mt++)
#pragma unroll
    for (int nt2 = 0; nt2 < 2; nt2++) {
        float vals[4] = {c[mt][nt2].x, c[mt][nt2].y, c[mt][nt2].z, c[mt][nt2].w};
#pragma unroll
        for (int rr = 0; rr < 2; rr++) {
            int rl = mt * 16 + (lane >> 2) + rr * 8;
            if (m0 + rl >= cnt) continue;
            int p = s_pid[rl];
#pragma unroll
            for (int cc2 = 0; cc2 < 2; cc2++) {
                int d = n0 + (ntb + nt2) * 8 + 2 * (lane & 3) + cc2;
                size_t rb = (size_t)(start + m0 + rl) * H + d;
                size_t pb = (size_t)p * H + d;
                float acc = vals[rr * 2 + cc2];
                if (mat == 0) {
                    __stcg(&g_zv[rb], sigf(__ldcg(&g_gz0[pb]) + acc));
                } else {
                    float r = sigf(__ldcg(&g_gr0[pb]) + acc);
                    __stcg(&g_mrv[rb], __ldcg(&g_memv[rb]) * r);
                }
            }
        }
    }
    __syncthreads();
    if (tid == 0) {
        __threadfence();
        atomicAdd(&g_bcnt[g], 1);
    }
}

// phaseC: BM=32, BN=128; waits bcnt==8
__device__ void phaseC(int start, int cnt, int gbase, int t, float* SBUF, int* s_pid) {
    int tid = threadIdx.x;
    int m0 = (t >> 2) * 32, n0 = (t & 3) * 128;
    int g = gbase + (m0 >> 5);
    float* sAh = SBUF;
    float* sAl = SBUF + 1152;
    int w = tid >> 5, lane = tid & 31;
    int ntb = w * 2;
    float4 c[2][2];
#pragma unroll
    for (int i = 0; i < 2; i++)
#pragma unroll
        for (int j = 0; j < 2; j++) c[i][j] = make_float4(0.f, 0.f, 0.f, 0.f);
    __syncthreads();
    if (tid == 0) waitcnt(&g_bcnt[g], 8);
    __syncthreads();
    if (tid < 32) s_pid[tid] = g_order[start + min(m0 + tid, cnt - 1)];
    int arow = tid >> 3, ak = (tid & 7) * 4;
    int rrow = start + min(m0 + arow, cnt - 1);
    for (int kc = 0; kc < H; kc += 32) {
        float4 a = __ldcg((const float4*)&g_mrv[(size_t)rrow * H + kc + ak]);
        float av[4] = {a.x, a.y, a.z, a.w};
#pragma unroll
        for (int j = 0; j < 4; j++) {
            int o = arow * 36 + ak + j;
            unsigned h = f2tf(av[j]);
            sAh[o] = __uint_as_float(h);
            sAl[o] = __uint_as_float(f2tf(av[j] - __uint_as_float(h)));
        }
        __syncthreads();
#pragma unroll
        for (int k8 = 0; k8 < 4; k8++) {
            unsigned ah[2][4], al[2][4];
#pragma unroll
            for (int mt = 0; mt < 2; mt++) {
                int ab = (mt * 16 + (lane >> 2)) * 36 + k8 * 8 + (lane & 3);
                ah[mt][0] = fau(sAh[ab]);     ah[mt][1] = fau(sAh[ab + 288]);
                ah[mt][2] = fau(sAh[ab + 4]); ah[mt][3] = fau(sAh[ab + 292]);
                al[mt][0] = fau(sAl[ab]);     al[mt][1] = fau(sAl[ab + 288]);
                al[mt][2] = fau(sAl[ab + 4]); al[mt][3] = fau(sAl[ab + 292]);
            }
#pragma unroll
            for (int nt2 = 0; nt2 < 2; nt2++) {
                size_t fo = (((size_t)5 * FR + (n0 >> 3) + ntb + nt2) * FR
                             + (kc >> 3) + k8) * 64 + lane * 2;
                uint2 bh2 = __ldg((const uint2*)&g_bfh[fo]);
                uint2 bl2 = __ldg((const uint2*)&g_bfl[fo]);
                mma3u(c[0][nt2], ah[0], al[0], bh2, bl2);
                mma3u(c[1][nt2], ah[1], al[1], bh2, bl2);
            }
        }
        __syncthreads();
    }
#pragma unroll
    for (int mt = 0; mt < 2; mt++)
#pragma unroll
    for (int nt2 = 0; nt2 < 2; nt2++) {
        float vals[4] = {c[mt][nt2].x, c[mt][nt2].y, c[mt][nt2].z, c[mt][nt2].w};
#pragma unroll
        for (int rr = 0; rr < 2; rr++) {
            int rl = mt * 16 + (lane >> 2) + rr * 8;
            if (m0 + rl >= cnt) continue;
            int p = s_pid[rl];
#pragma unroll
            for (int cc2 = 0; cc2 < 2; cc2++) {
                int d = n0 + (ntb + nt2) * 8 + 2 * (lane & 3) + cc2;
                size_t rb = (size_t)(start + m0 + rl) * H + d;
                size_t pb = (size_t)p * H + d;
                float cval = tanhf(__ldcg(&g_gh0[pb]) + vals[rr * 2 + cc2]);
                float z = __ldcg(&g_zv[rb]);
                float mem = __ldcg(&g_memv[rb]);
                __stcg(&g_nodeh[(size_t)(NLEAF + p) * H + d], z * mem + (1.f - z) * cval);
            }
        }
    }
}

__global__ void __launch_bounds__(256) k_main(
    const int* __restrict__ tree,
    const float* __restrict__ Uz, const float* __restrict__ Ur,
    const float* __restrict__ Uh)
{
    __shared__ float SBUF[4608];
    __shared__ float s_sc[128], s_p[128];
    __shared__ int s_child[DEG], s_pid[32];
    int nb = gridDim.x;
    int sense = 0;
    int tid = threadIdx.x;
    int gstride = nb * 256;

    // ---- leveling prologue ----
    for (int p = blockIdx.x * 256 + tid; p < NPAR; p += gstride) {
        int lv = 0;
#pragma unroll
        for (int k = 0; k < DEG; k++) {
            int c = tree[p * DEG + k];
            if (c >= NLEAF) {
                int v;
                while ((v = atomicAdd(&g_lvl[c - NLEAF], 0)) < 0) __nanosleep(40);
                lv = max(lv, v + 1);
            }
        }
        if (lv > LMAX - 1) lv = LMAX - 1;
        atomicExch(&g_lvl[p], lv);
    }
    gridbar(nb, sense);
    for (int p = blockIdx.x * 256 + tid; p < NPAR; p += gstride)
        atomicAdd(&g_hist[g_lvl[p]], 1);
    gridbar(nb, sense);
    if (blockIdx.x == 0 && tid == 0) {
        int acc = 0, nl = 1, G = 0;
        for (int i = 0; i < LMAX; i++) {
            g_lstart[i] = acc; g_lofs[i] = acc;
            int c = g_hist[i];
            acc += c;
            g_gbase[i] = G;
            G += (c > 0) ? ((c < 32) ? 1 : ((c + 31) >> 5)) : 0;
            if (c > 0) nl = i + 1;
        }
        g_nlev = nl;
    }
    gridbar(nb, sense);
    for (int p = blockIdx.x * 256 + tid; p < NPAR; p += gstride)
        g_order[atomicAdd(&g_lofs[g_lvl[p]], 1)] = p;
    gridbar(nb, sense);

    int nlev = g_nlev;
    for (int l = 0; l < nlev; l++) {
        int start = g_lstart[l], cnt = g_hist[l];
        if (cnt == 0) continue;
        int gbase = g_gbase[l];
        for (int j = blockIdx.x; j < cnt; j += nb)
            phaseA(start + j, start, gbase, tree, SBUF, s_child, s_sc, s_p);
        if (cnt < 32) {
            coopB(start, cnt, gbase, Uz, Ur);
            coopC(start, cnt, gbase, Uh);
        } else {
            int mt = (cnt + 31) >> 5;
            int ntB = mt * 8;
            for (int t = blockIdx.x; t < ntB; t += nb)
                phaseB(start, cnt, gbase, t, SBUF, s_pid);
            int ntC = mt * 4;
            for (int t = blockIdx.x; t < ntC; t += nb)
                phaseC(start, cnt, gbase, t, SBUF, s_pid);
        }
        gridbar(nb, sense);
    }
}

// ---------------- reductions ----------------
__global__ void k_redmax() {
    int tid = threadIdx.x;
    int b = blockIdx.x;
    const float* base = g_nodeh + (size_t)NLEAF * H;
    float m = -3.4e38f;
    for (int p = b * RED_CHUNK; p < (b + 1) * RED_CHUNK; p++)
        m = fmaxf(m, base[(size_t)p * H + tid]);
    g_pmax[b * H + tid] = m;
}

__global__ void k_final(const float* __restrict__ Wo, const float* __restrict__ bo,
                        float* __restrict__ out) {
    __shared__ float s_f[H];
    __shared__ float s_logit[NCLASS];
    int tid = threadIdx.x;   // 512
    float m = g_pmax[tid];
    for (int b = 1; b < NB_RED; b++) m = fmaxf(m, g_pmax[b * H + tid]);
    s_f[tid] = m;
    __syncthreads();
    int w = tid >> 5, lane = tid & 31;
    if (w < NCLASS) {
        float acc = 0.f;
        for (int j = lane; j < H; j += 32) acc += Wo[w * H + j] * s_f[j];
#pragma unroll
        for (int o = 16; o; o >>= 1) acc += __shfl_down_sync(0xffffffffu, acc, o);
        if (lane == 0) s_logit[w] = acc + bo[w];
    }
    __syncthreads();
    if (tid == 0) {
        float mx = s_logit[0];
        for (int i = 1; i < NCLASS; i++) mx = fmaxf(mx, s_logit[i]);
        float e[NCLASS], s = 0.f;
        for (int i = 0; i < NCLASS; i++) { e[i] = __expf(s_logit[i] - mx); s += e[i]; }
        for (int i = 0; i < NCLASS; i++) out[i] = e[i] / s;
    }
}

extern "C" void kernel_launch(void* const* d_in, const int* in_sizes, int n_in,
                              void* d_out, int out_size) {
    const float* x_word  = (const float*)d_in[0];
    const int*   x_index = (const int*)  d_in[1];
    const int*   tree    = (const int*)  d_in[2];
    const float* E_bu    = (const float*)d_in[3];
    const float* W_z = (const float*)d_in[4];
    const float* U_z = (const float*)d_in[5];
    const float* b_z = (const float*)d_in[6];
    const float* W_r = (const float*)d_in[7];
    const float* U_r = (const float*)d_in[8];
    const float* b_r = (const float*)d_in[9];
    const float* W_h = (const float*)d_in[10];
    const float* U_h = (const float*)d_in[11];
    const float* b_h = (const float*)d_in[12];
    const float* W_out = (const float*)d_in[13];
    const float* b_out = (const float*)d_in[14];
    float* out = (float*)d_out;

    static int nb_main = 0;
    if (nb_main == 0) {
        int dev = 0; cudaGetDevice(&dev);
        int nsm = 0; cudaDeviceGetAttribute(&nsm, cudaDevAttrMultiProcessorCount, dev);
        int perSM = 0;
        cudaOccupancyMaxActiveBlocksPerMultiprocessor(&perSM, k_main, 256, 0);
        if (perSM < 1) perSM = 1;
        nb_main = nsm * perSM;
    }

    dim3 tb(32, 8), tg((VOCAB + 31) / 32, H / 32);
    k_setup<<<tg, tb>>>(E_bu);
    k_split<<<(6 * FR * FR * 32 + 255) / 256, 256>>>(W_z, W_r, W_h, U_z, U_r, U_h);
    k_embed<<<NTOT, 128>>>(x_word, x_index);
    k_pregemm<<<dim3((NPAR + 127) / 128, H / 64, 3), 256>>>(b_z, b_r, b_h);
    k_main<<<nb_main, 256>>>(tree, U_z, U_r, U_h);
    k_redmax<<<NB_RED, H>>>();
    k_final<<<1, H>>>(W_out, b_out, out);
}